// round 16
// baseline (speedup 1.0000x reference)
#include <cuda_runtime.h>
#include <cuda_fp16.h>
#include <cstdint>

// ---------------------------------------------------------------------------
// Problem constants
// ---------------------------------------------------------------------------
#define BATCH    8192
#define HIDDEN   2048
#define NQ       16
#define HALF_DIM 1024

// GEMM tiling: CTA 64(M)x64(N), 2 warps (1Mx2N of 64x32), 8 CTAs/SM.
// BOTH operands fragment-major in gmem -> LDG straight to registers.
// Register double-buffer, barrier-free mainloop. 8 small CTAs/SM maximize
// phase diversity across the SM (anti-convoy; R5 evidence extended).
#define BM      64
#define BN      64
#define THREADS 64
#define M_TILES (BATCH / BM)            // 128
#define N_TILES (NQ * HALF_DIM / BN)    // 256
#define NTILES  (M_TILES * N_TILES)     // 32768
#define KSTEPS  (HIDDEN / 16)           // 128 k16 steps

// Fragment record strides (bytes)
//   A record (m16,k16): 32 lanes x 16B = 512B; addr = (m16*128 + k16)*512 + lane*16
//   B record (k16,n16): 32 lanes x 16B = 512B; addr = (k16*1024 + n16)*512 + lane*16
//     lane 16B = {n8even.r0, n8even.r1, n8odd.r0, n8odd.r1}
#define A_K16_STRIDE 512u
#define A_M16_STRIDE 65536u             // 128 * 512
#define B_N16_STRIDE 512u
#define B_K16_STRIDE 524288u            // 1024 * 512

// fp16 fragment scratch
__device__ __align__(1024) __half g_Xf[(size_t)BATCH * HIDDEN + 512];
__device__ __align__(1024) __half g_Wf[(size_t)NQ * HALF_DIM * HIDDEN + 8192];

// ---------------------------------------------------------------------------
// Helpers
// ---------------------------------------------------------------------------
__device__ __forceinline__ void mma16816(float* c, const uint32_t* a, uint2 b) {
    asm volatile(
        "mma.sync.aligned.m16n8k16.row.col.f32.f16.f16.f32 "
        "{%0,%1,%2,%3}, {%4,%5,%6,%7}, {%8,%9}, {%0,%1,%2,%3};"
        : "+f"(c[0]), "+f"(c[1]), "+f"(c[2]), "+f"(c[3])
        : "r"(a[0]), "r"(a[1]), "r"(a[2]), "r"(a[3]), "r"(b.x), "r"(b.y));
}

// ---------------------------------------------------------------------------
// Fused prepass: one launch, block-range dispatch (R14/R15, at DRAM floor).
//   blocks [0, 8192)      : W1 -> B fragment records (smem-tiled, coalesced)
//   blocks [8192, 12288)  : x  -> A fragment records (smem-tiled, coalesced)
//   blocks [12288, 12800) : out = b2 broadcast
// ---------------------------------------------------------------------------
#define PS 260                            // smem row stride (floats)
#define PREP_SMEM (16 * PS * 4)           // 16640 bytes

__global__ void prep_all_kernel(const float* __restrict__ W1,
                                const float* __restrict__ x,
                                float* __restrict__ out,
                                const float* __restrict__ b2) {
    extern __shared__ float s[];
    int bid = blockIdx.x;
    int t   = threadIdx.x;                // 256 threads

    if (bid < 8192) {
        // ---- W prep: block = (nb, k16, q) ----
        int nb  = bid & 3;
        int k16 = (bid >> 2) & 127;
        int q   = bid >> 9;
        const float* src = W1 + ((size_t)q * HIDDEN + k16 * 16) * HALF_DIM + nb * 256;
#pragma unroll
        for (int i = 0; i < 16; i++)
            s[i * PS + t] = src[(size_t)i * HALF_DIM + t];
        __syncthreads();
        int lane = t & 31;
        int w    = t >> 5;
#pragma unroll
        for (int p = 0; p < 2; p++) {
            int n16l = w * 2 + p;                   // 0..15
            int nl   = n16l * 16 + (lane >> 2);     // n8even col within 256
            int kb   = (lane & 3) << 1;
            union { __half2 h; uint32_t u; } e0, e1, o0, o1;
            e0.h = __floats2half2_rn(s[(kb + 0) * PS + nl],     s[(kb + 1) * PS + nl]);
            e1.h = __floats2half2_rn(s[(kb + 8) * PS + nl],     s[(kb + 9) * PS + nl]);
            o0.h = __floats2half2_rn(s[(kb + 0) * PS + nl + 8], s[(kb + 1) * PS + nl + 8]);
            o1.h = __floats2half2_rn(s[(kb + 8) * PS + nl + 8], s[(kb + 9) * PS + nl + 8]);
            int n16g = q * 64 + nb * 16 + n16l;     // 0..1023
            reinterpret_cast<uint4*>(g_Wf)[((size_t)k16 * 1024 + n16g) * 32 + lane] =
                make_uint4(e0.u, e1.u, o0.u, o1.u);
        }
    } else if (bid < 12288) {
        // ---- X prep: block = (m16, kb of 256 cols) ----
        int idx = bid - 8192;
        int m16 = idx >> 3;
        int kb  = idx & 7;
        const float* src = x + (size_t)(m16 * 16) * HIDDEN + kb * 256;
#pragma unroll
        for (int i = 0; i < 16; i++)
            s[i * PS + t] = src[(size_t)i * HIDDEN + t];
        __syncthreads();
        int lane = t & 31;
        int w    = t >> 5;
#pragma unroll
        for (int p = 0; p < 2; p++) {
            int k16l = w * 2 + p;                   // 0..15
            int r    = lane >> 2;
            int base = k16l * 16 + ((lane & 3) << 1);
            union { __half2 h; uint32_t u; } a0, a1, a2, a3;
            a0.h = __floats2half2_rn(s[r * PS + base],           s[r * PS + base + 1]);
            a1.h = __floats2half2_rn(s[(r + 8) * PS + base],     s[(r + 8) * PS + base + 1]);
            a2.h = __floats2half2_rn(s[r * PS + base + 8],       s[r * PS + base + 9]);
            a3.h = __floats2half2_rn(s[(r + 8) * PS + base + 8], s[(r + 8) * PS + base + 9]);
            int rec = m16 * 128 + kb * 16 + k16l;
            reinterpret_cast<uint4*>(g_Xf)[(size_t)rec * 32 + lane] =
                make_uint4(a0.u, a1.u, a2.u, a3.u);
        }
    } else {
        // ---- out init ----
        int i = (bid - 12288) * 256 + t;
        out[i] = b2[i & (NQ - 1)];
    }
}

// ---------------------------------------------------------------------------
// Main GEMM + fused GELU/GEMV epilogue — all-register, barrier-free mainloop
// ---------------------------------------------------------------------------
__device__ __forceinline__ void loadAB(uint4* a, uint4* b,
                                       const char* Ap, const char* Bp) {
    b[0] = __ldg(reinterpret_cast<const uint4*>(Bp));
    b[1] = __ldg(reinterpret_cast<const uint4*>(Bp + B_N16_STRIDE));
#pragma unroll
    for (int mi = 0; mi < 4; mi++)
        a[mi] = __ldg(reinterpret_cast<const uint4*>(Ap + mi * A_M16_STRIDE));
}
__device__ __forceinline__ void mmastep(float acc[4][4][4], uint4* a, uint4* b) {
    const uint2* bv = reinterpret_cast<const uint2*>(b);   // register alias
#pragma unroll
    for (int mi = 0; mi < 4; mi++)
#pragma unroll
        for (int nj = 0; nj < 4; nj++)
            mma16816(acc[mi][nj], reinterpret_cast<uint32_t*>(&a[mi]), bv[nj]);
}

__global__ void __launch_bounds__(THREADS, 8)
gemm_kernel(const float* __restrict__ b1, const float* __restrict__ W2,
            float* __restrict__ out) {
    __shared__ float par[128];          // b1[0:64] | w2[64:128]
    const int tid = threadIdx.x;
    const int wid = tid >> 5;
    const int lid = tid & 31;
    const int wn  = wid;                // N slab (32 cols), 0..1 (single M slab)

    // Supertile swizzle: 8(M) x 16(N) tiles per 128-CTA group; 16x16 groups.
    int cta    = blockIdx.x;
    int super  = cta >> 7;              // 0..255
    int within = cta & 127;
    int m_tile = (super & 15) * 8 + (within & 7);     // 0..127
    int n_tile = (super >> 4) * 16 + (within >> 3);   // 0..255
    int m0     = m_tile * BM;
    int q      = n_tile >> 4;
    int nn     = (n_tile & 15) * BN;

    // Fragment base pointers (advance by one k16 stride per step)
    const char* Ap = (const char*)g_Xf
                   + (size_t)(m_tile * 4) * A_M16_STRIDE + lid * 16;
    const char* Bp = (const char*)g_Wf
                   + ((size_t)(n_tile * 4 + wn * 2) * 32 + lid) * 16;

    // Epilogue params (single barrier of the whole kernel)
    par[tid]      = b1[q * HALF_DIM + nn + tid];
    par[tid + 64] = W2[q * HALF_DIM + nn + tid];
    __syncthreads();

    float acc[4][4][4];
#pragma unroll
    for (int mi = 0; mi < 4; mi++)
#pragma unroll
        for (int nj = 0; nj < 4; nj++)
#pragma unroll
            for (int e = 0; e < 4; e++) acc[mi][nj][e] = 0.0f;

    // Register double-buffer, prefetch distance 1, peeled tail (last load is
    // step 127 exactly — no OOB prefetch).
    uint4 a0[4], a1[4];
    uint4 b0[2], b1f[2];
    loadAB(a0, b0, Ap, Bp);
    Ap += A_K16_STRIDE; Bp += B_K16_STRIDE;

    for (int s = 0; s < KSTEPS - 2; s += 2) {
        loadAB(a1, b1f, Ap, Bp);
        Ap += A_K16_STRIDE; Bp += B_K16_STRIDE;
        mmastep(acc, a0, b0);
        loadAB(a0, b0, Ap, Bp);
        Ap += A_K16_STRIDE; Bp += B_K16_STRIDE;
        mmastep(acc, a1, b1f);
    }
    loadAB(a1, b1f, Ap, Bp);            // step 127
    mmastep(acc, a0, b0);               // step 126
    mmastep(acc, a1, b1f);              // step 127

    // Epilogue: h = acc + b1; gelu(h) = h * Phi(h); dot with W2; quad-reduce.
    const float* b1s = par;
    const float* w2s = par + 64;
#pragma unroll
    for (int mi = 0; mi < 4; mi++) {
#pragma unroll
        for (int rh = 0; rh < 2; rh++) {
            float v = 0.0f;
#pragma unroll
            for (int nj = 0; nj < 4; nj++) {
                int ncol = wn * 32 + nj * 8 + 2 * (lid & 3);
#pragma unroll
                for (int e = 0; e < 2; e++) {
                    float h = acc[mi][nj][rh * 2 + e] + b1s[ncol + e];
                    v += h * normcdff(h) * w2s[ncol + e];
                }
            }
            v += __shfl_xor_sync(0xFFFFFFFFu, v, 1);
            v += __shfl_xor_sync(0xFFFFFFFFu, v, 2);
            if ((lid & 3) == 0) {
                int mrow = m0 + mi * 16 + rh * 8 + (lid >> 2);
                atomicAdd(out + (size_t)mrow * NQ + q, v);
            }
        }
    }
}

// ---------------------------------------------------------------------------
// Launch
// ---------------------------------------------------------------------------
extern "C" void kernel_launch(void* const* d_in, const int* in_sizes, int n_in,
                              void* d_out, int out_size) {
    const float* x  = (const float*)d_in[0];
    const float* W1 = (const float*)d_in[1];
    const float* b1 = (const float*)d_in[2];
    const float* W2 = (const float*)d_in[3];
    const float* b2 = (const float*)d_in[4];
    float* out = (float*)d_out;
    (void)in_sizes; (void)n_in; (void)out_size;

    prep_all_kernel<<<12800, 256, PREP_SMEM>>>(W1, x, out, b2);
    gemm_kernel<<<NTILES, THREADS>>>(b1, W2, out);
}

// round 17
// speedup vs baseline: 1.0269x; 1.0269x over previous
#include <cuda_runtime.h>
#include <cuda_fp16.h>
#include <cstdint>

// ---------------------------------------------------------------------------
// Problem constants
// ---------------------------------------------------------------------------
#define BATCH    8192
#define HIDDEN   2048
#define NQ       16
#define HALF_DIM 1024

// GEMM tiling: CTA 128(M)x64(N), 4 warps (2Mx2N of 64x32), 4 CTAs/SM.
// BOTH operands fragment-major in gmem -> LDG.CONSTANT straight to registers.
// Register double-buffer, barrier-free mainloop. (R15 measured-best: 1239.5us,
// tensor 75.4% — the legacy-HMMA plateau on sm_103a; tcgen05 is ptxas-blocked
// at compute_103, and 10 structural variants confirmed this envelope.)
#define BM      128
#define BN      64
#define THREADS 128
#define M_TILES (BATCH / BM)            // 64
#define N_TILES (NQ * HALF_DIM / BN)    // 256
#define NTILES  (M_TILES * N_TILES)     // 16384
#define KSTEPS  (HIDDEN / 16)           // 128 k16 steps

// Fragment record strides (bytes)
//   A record (m16,k16): 32 lanes x 16B = 512B; addr = (m16*128 + k16)*512 + lane*16
//   B record (k16,n16): 32 lanes x 16B = 512B; addr = (k16*1024 + n16)*512 + lane*16
//     lane 16B = {n8even.r0, n8even.r1, n8odd.r0, n8odd.r1}
#define A_K16_STRIDE 512u
#define A_M16_STRIDE 65536u             // 128 * 512
#define B_N16_STRIDE 512u
#define B_K16_STRIDE 524288u            // 1024 * 512

// fp16 fragment scratch
__device__ __align__(1024) __half g_Xf[(size_t)BATCH * HIDDEN + 512];
__device__ __align__(1024) __half g_Wf[(size_t)NQ * HALF_DIM * HIDDEN + 8192];

// ---------------------------------------------------------------------------
// Helpers
// ---------------------------------------------------------------------------
__device__ __forceinline__ void mma16816(float* c, const uint32_t* a, uint2 b) {
    asm volatile(
        "mma.sync.aligned.m16n8k16.row.col.f32.f16.f16.f32 "
        "{%0,%1,%2,%3}, {%4,%5,%6,%7}, {%8,%9}, {%0,%1,%2,%3};"
        : "+f"(c[0]), "+f"(c[1]), "+f"(c[2]), "+f"(c[3])
        : "r"(a[0]), "r"(a[1]), "r"(a[2]), "r"(a[3]), "r"(b.x), "r"(b.y));
}

// ---------------------------------------------------------------------------
// Fused prepass: one launch, block-range dispatch (at the DRAM floor).
//   blocks [0, 8192)      : W1 -> B fragment records (smem-tiled, coalesced)
//   blocks [8192, 12288)  : x  -> A fragment records (smem-tiled, coalesced)
//   blocks [12288, 12800) : out = b2 broadcast
// ---------------------------------------------------------------------------
#define PS 260                            // smem row stride (floats)
#define PREP_SMEM (16 * PS * 4)           // 16640 bytes

__global__ void prep_all_kernel(const float* __restrict__ W1,
                                const float* __restrict__ x,
                                float* __restrict__ out,
                                const float* __restrict__ b2) {
    extern __shared__ float s[];
    int bid = blockIdx.x;
    int t   = threadIdx.x;                // 256 threads

    if (bid < 8192) {
        // ---- W prep: block = (nb, k16, q) ----
        int nb  = bid & 3;
        int k16 = (bid >> 2) & 127;
        int q   = bid >> 9;
        const float* src = W1 + ((size_t)q * HIDDEN + k16 * 16) * HALF_DIM + nb * 256;
#pragma unroll
        for (int i = 0; i < 16; i++)
            s[i * PS + t] = src[(size_t)i * HALF_DIM + t];
        __syncthreads();
        int lane = t & 31;
        int w    = t >> 5;
#pragma unroll
        for (int p = 0; p < 2; p++) {
            int n16l = w * 2 + p;                   // 0..15
            int nl   = n16l * 16 + (lane >> 2);     // n8even col within 256
            int kb   = (lane & 3) << 1;
            union { __half2 h; uint32_t u; } e0, e1, o0, o1;
            e0.h = __floats2half2_rn(s[(kb + 0) * PS + nl],     s[(kb + 1) * PS + nl]);
            e1.h = __floats2half2_rn(s[(kb + 8) * PS + nl],     s[(kb + 9) * PS + nl]);
            o0.h = __floats2half2_rn(s[(kb + 0) * PS + nl + 8], s[(kb + 1) * PS + nl + 8]);
            o1.h = __floats2half2_rn(s[(kb + 8) * PS + nl + 8], s[(kb + 9) * PS + nl + 8]);
            int n16g = q * 64 + nb * 16 + n16l;     // 0..1023
            reinterpret_cast<uint4*>(g_Wf)[((size_t)k16 * 1024 + n16g) * 32 + lane] =
                make_uint4(e0.u, e1.u, o0.u, o1.u);
        }
    } else if (bid < 12288) {
        // ---- X prep: block = (m16, kb of 256 cols) ----
        int idx = bid - 8192;
        int m16 = idx >> 3;
        int kb  = idx & 7;
        const float* src = x + (size_t)(m16 * 16) * HIDDEN + kb * 256;
#pragma unroll
        for (int i = 0; i < 16; i++)
            s[i * PS + t] = src[(size_t)i * HIDDEN + t];
        __syncthreads();
        int lane = t & 31;
        int w    = t >> 5;
#pragma unroll
        for (int p = 0; p < 2; p++) {
            int k16l = w * 2 + p;                   // 0..15
            int r    = lane >> 2;
            int base = k16l * 16 + ((lane & 3) << 1);
            union { __half2 h; uint32_t u; } a0, a1, a2, a3;
            a0.h = __floats2half2_rn(s[r * PS + base],           s[r * PS + base + 1]);
            a1.h = __floats2half2_rn(s[(r + 8) * PS + base],     s[(r + 8) * PS + base + 1]);
            a2.h = __floats2half2_rn(s[r * PS + base + 8],       s[r * PS + base + 9]);
            a3.h = __floats2half2_rn(s[(r + 8) * PS + base + 8], s[(r + 8) * PS + base + 9]);
            int rec = m16 * 128 + kb * 16 + k16l;
            reinterpret_cast<uint4*>(g_Xf)[(size_t)rec * 32 + lane] =
                make_uint4(a0.u, a1.u, a2.u, a3.u);
        }
    } else {
        // ---- out init ----
        int i = (bid - 12288) * 256 + t;
        out[i] = b2[i & (NQ - 1)];
    }
}

// ---------------------------------------------------------------------------
// Main GEMM + fused GELU/GEMV epilogue — all-register, barrier-free mainloop
// ---------------------------------------------------------------------------
__device__ __forceinline__ void loadAB(uint4* a, uint4* b,
                                       const char* Ap, const char* Bp) {
    // B first: B lines are shared by twin warps (wm=0/1) — early issue raises
    // the L1-hit chance for the second reader.
    b[0] = __ldg(reinterpret_cast<const uint4*>(Bp));
    b[1] = __ldg(reinterpret_cast<const uint4*>(Bp + B_N16_STRIDE));
#pragma unroll
    for (int mi = 0; mi < 4; mi++)
        a[mi] = __ldg(reinterpret_cast<const uint4*>(Ap + mi * A_M16_STRIDE));
}
__device__ __forceinline__ void mmastep(float acc[4][4][4], uint4* a, uint4* b) {
    const uint2* bv = reinterpret_cast<const uint2*>(b);   // register alias, no copies
#pragma unroll
    for (int mi = 0; mi < 4; mi++)
#pragma unroll
        for (int nj = 0; nj < 4; nj++)
            mma16816(acc[mi][nj], reinterpret_cast<uint32_t*>(&a[mi]), bv[nj]);
}

__global__ void __launch_bounds__(THREADS, 4)
gemm_kernel(const float* __restrict__ b1, const float* __restrict__ W2,
            float* __restrict__ out) {
    __shared__ float par[128];          // b1[0:64] | w2[64:128]
    const int tid = threadIdx.x;
    const int wid = tid >> 5;
    const int lid = tid & 31;
    const int wm  = wid >> 1;           // M slab (64 rows), 0..1
    const int wn  = wid & 1;            // N slab (32 cols), 0..1

    // Supertile swizzle: 8(M) x 16(N) CTAs per 128-CTA group
    int cta    = blockIdx.x;
    int super  = cta >> 7;
    int within = cta & 127;
    int m_tile = (super & 7) * 8 + (within & 7);     // 0..63
    int n_tile = (super >> 3) * 16 + (within >> 3);  // 0..255
    int m0     = m_tile * BM;
    int q      = n_tile >> 4;
    int nn     = (n_tile & 15) * BN;

    // Fragment base pointers (advance by one k16 stride per step)
    const char* Ap = (const char*)g_Xf
                   + (size_t)(m_tile * 8 + wm * 4) * A_M16_STRIDE + lid * 16;
    const char* Bp = (const char*)g_Wf
                   + ((size_t)(n_tile * 4 + wn * 2) * 32 + lid) * 16;

    // Epilogue params (single barrier of the whole kernel)
    {
        int col = tid & 63;
        const float* src = (tid < 64) ? b1 : W2;
        par[tid] = src[q * HALF_DIM + nn + col];
    }
    __syncthreads();

    float acc[4][4][4];
#pragma unroll
    for (int mi = 0; mi < 4; mi++)
#pragma unroll
        for (int nj = 0; nj < 4; nj++)
#pragma unroll
            for (int e = 0; e < 4; e++) acc[mi][nj][e] = 0.0f;

    // Register double-buffer, prefetch distance 1, peeled tail (last load is
    // step 127 exactly — no OOB prefetch).
    uint4 a0[4], a1[4];
    uint4 b0[2], b1f[2];
    loadAB(a0, b0, Ap, Bp);
    Ap += A_K16_STRIDE; Bp += B_K16_STRIDE;

    for (int s = 0; s < KSTEPS - 2; s += 2) {
        loadAB(a1, b1f, Ap, Bp);
        Ap += A_K16_STRIDE; Bp += B_K16_STRIDE;
        mmastep(acc, a0, b0);
        loadAB(a0, b0, Ap, Bp);
        Ap += A_K16_STRIDE; Bp += B_K16_STRIDE;
        mmastep(acc, a1, b1f);
    }
    loadAB(a1, b1f, Ap, Bp);            // step 127
    mmastep(acc, a0, b0);               // step 126
    mmastep(acc, a1, b1f);              // step 127

    // Epilogue: h = acc + b1; gelu(h) = h * Phi(h); dot with W2; quad-reduce.
    const float* b1s = par;
    const float* w2s = par + 64;
#pragma unroll
    for (int mi = 0; mi < 4; mi++) {
#pragma unroll
        for (int rh = 0; rh < 2; rh++) {
            float v = 0.0f;
#pragma unroll
            for (int nj = 0; nj < 4; nj++) {
                int ncol = wn * 32 + nj * 8 + 2 * (lid & 3);
#pragma unroll
                for (int e = 0; e < 2; e++) {
                    float h = acc[mi][nj][rh * 2 + e] + b1s[ncol + e];
                    v += h * normcdff(h) * w2s[ncol + e];
                }
            }
            v += __shfl_xor_sync(0xFFFFFFFFu, v, 1);
            v += __shfl_xor_sync(0xFFFFFFFFu, v, 2);
            if ((lid & 3) == 0) {
                int mrow = m0 + wm * 64 + mi * 16 + rh * 8 + (lid >> 2);
                atomicAdd(out + (size_t)mrow * NQ + q, v);
            }
        }
    }
}

// ---------------------------------------------------------------------------
// Launch
// ---------------------------------------------------------------------------
extern "C" void kernel_launch(void* const* d_in, const int* in_sizes, int n_in,
                              void* d_out, int out_size) {
    const float* x  = (const float*)d_in[0];
    const float* W1 = (const float*)d_in[1];
    const float* b1 = (const float*)d_in[2];
    const float* W2 = (const float*)d_in[3];
    const float* b2 = (const float*)d_in[4];
    float* out = (float*)d_out;
    (void)in_sizes; (void)n_in; (void)out_size;

    prep_all_kernel<<<12800, 256, PREP_SMEM>>>(W1, x, out, b2);
    gemm_kernel<<<NTILES, THREADS>>>(b1, W2, out);
}